// round 17
// baseline (speedup 1.0000x reference)
#include <cuda_runtime.h>

// B=256 batches, N=128 neurons, E=4N=512 state dims.
// Output layout: [ydot (B*512 floats)] [J (B*512*512 floats)]
#define NN 128
#define BB 256
#define EE 512

__device__ __forceinline__ float rcp_fast(float x) {
    float r;
    asm("rcp.approx.f32 %0, %1;" : "=f"(r) : "f"(x));
    return r;
}

// ---------------------------------------------------------------------
// ONE kernel, ONE launch. grid = (256, 129), block = 256.
//   blockIdx.y == 0, x <  64  : POINT block for batches {4x .. 4x+3}
//   blockIdx.y == 0, x >= 64  : immediate exit
//   blockIdx.y >= 1           : FILL block (proven store structure),
//                               batch pair = y-1, row pair = x.
// Point blocks are first in linear block order -> first waves, fully
// overlapped by the 268 MB fill stream. They write ydot and J's
// V-diagonal float4s -- bytes fill blocks never touch -> no ordering.
// All reductions fixed-order (butterfly shfl + shared tree) ->
// bit-deterministic.
// ---------------------------------------------------------------------
__global__ void __launch_bounds__(256, 8)
hh_fused_kernel(const float* __restrict__ y,     const float* __restrict__ Ic,
                const float* __restrict__ C,
                const float* __restrict__ g_Na,  const float* __restrict__ E_Na,
                const float* __restrict__ g_K,   const float* __restrict__ E_K,
                const float* __restrict__ g_L,   const float* __restrict__ E_L,
                const float* __restrict__ m_inf, const float* __restrict__ tau_m,
                const float* __restrict__ h_inf, const float* __restrict__ tau_h,
                const float* __restrict__ n_inf, const float* __restrict__ tau_n,
                const float* __restrict__ gC,
                float* __restrict__ ydot,
                float* __restrict__ J) {
    // static smem used only by point blocks (~5.5 KB; no occupancy impact)
    __shared__ float invCs[NN];
    __shared__ float Vs   [4 * NN];
    __shared__ float rs   [NN];
    __shared__ float wv   [4 * NN];     // wv[q*NN + row]
    __shared__ float red  [NN];

    if (blockIdx.y != 0) {
        // ================= FILL path =================
        const int j    = threadIdx.x & 127;
        const int half = threadIdx.x >> 7;
        const int r    = blockIdx.x * 2 + half;       // 0..511, warp-uniform
        const int b    = blockIdx.y - 1;              // batches b and b+128
        const int comp = r & 3;
        const int i    = r >> 2;

        float4 o = make_float4(0.f, 0.f, 0.f, 0.f);
        if (comp == 0) {
            o.x = -gC[i * NN + j] * rcp_fast(C[j]);   // 1 MUFU + 1 FMUL
        } else if (j == i) {
            const float* tau = (comp == 1) ? tau_m : (comp == 2) ? tau_h : tau_n;
            reinterpret_cast<float*>(&o)[comp] = -rcp_fast(tau[i]);
        }

        const bool skip = (comp == 0) & (j == i);     // point owns these bytes
        if (!skip) {
            unsigned idx0 = (unsigned)b * (EE * NN) + (unsigned)r * NN + j;
            unsigned idx1 = idx0 + 128u * (EE * NN);
            __stcs(reinterpret_cast<float4*>(J) + idx0, o);
            __stcs(reinterpret_cast<float4*>(J) + idx1, o);
        }
        return;
    }

    // ==================== POINT path ====================
    if (blockIdx.x >= 64) return;                     // 64 active blocks

    const int tid  = threadIdx.x;
    const int lane = tid & 31;
    const int wa   = tid >> 5;                        // warp 0..7
    const int b0   = blockIdx.x * 4;                  // 4 batches per block

    if (tid < NN) invCs[tid] = 1.f / C[tid];
    #pragma unroll
    for (int e = tid; e < 4 * NN; e += 256) {         // V of 4 batches
        int q = e >> 7, ii = e & 127;
        Vs[e] = y[(size_t)(b0 + q) * EE + 4 * ii];
    }
    __syncthreads();

    // per-lane constants: columns 4*lane..4*lane+3
    const float4 iv  = reinterpret_cast<float4*>(invCs)[lane];
    const float4 va0 = reinterpret_cast<float4*>(Vs)[lane];
    const float4 va1 = reinterpret_cast<float4*>(Vs + NN)[lane];
    const float4 va2 = reinterpret_cast<float4*>(Vs + 2 * NN)[lane];
    const float4 va3 = reinterpret_cast<float4*>(Vs + 3 * NN)[lane];

    // warp-per-row GEMV: rows wa*16 .. wa*16+15; g reused for 4 batches
    #pragma unroll 4
    for (int rr = 0; rr < 16; rr++) {
        const int row = wa * 16 + rr;
        float4 g = reinterpret_cast<const float4*>(gC)[row * 32 + lane];
        float tx = g.x * iv.x, ty = g.y * iv.y, tz = g.z * iv.z, tw = g.w * iv.w;
        float prs = (tx + ty) + (tz + tw);            // row-sum partial
        float p0 = (tx * va0.x + ty * va0.y) + (tz * va0.z + tw * va0.w);
        float p1 = (tx * va1.x + ty * va1.y) + (tz * va1.z + tw * va1.w);
        float p2 = (tx * va2.x + ty * va2.y) + (tz * va2.z + tw * va2.w);
        float p3 = (tx * va3.x + ty * va3.y) + (tz * va3.z + tw * va3.w);
        #pragma unroll
        for (int s = 16; s > 0; s >>= 1) {            // butterfly, fixed order
            prs += __shfl_xor_sync(0xFFFFFFFFu, prs, s);
            p0  += __shfl_xor_sync(0xFFFFFFFFu, p0, s);
            p1  += __shfl_xor_sync(0xFFFFFFFFu, p1, s);
            p2  += __shfl_xor_sync(0xFFFFFFFFu, p2, s);
            p3  += __shfl_xor_sync(0xFFFFFFFFu, p3, s);
        }
        if (lane == 0) {
            rs[row] = prs;
            wv[0 * NN + row] = p0;
            wv[1 * NN + row] = p1;
            wv[2 * NN + row] = p2;
            wv[3 * NN + row] = p3;
        }
    }
    __syncthreads();

    // sumGC: deterministic shared tree over the 128 row sums
    if (tid < NN) red[tid] = rs[tid];
    __syncthreads();
    #pragma unroll
    for (int s = 64; s > 0; s >>= 1) {
        if (tid < s) red[tid] += red[tid + s];
        __syncthreads();
    }
    const float sumGC = red[0];

    // HH dynamics: 2 (batch, neuron) pairs per thread
    #pragma unroll
    for (int e = tid; e < 4 * NN; e += 256) {
        const int q = e >> 7;
        const int i = e & 127;
        const int b = b0 + q;

        float4 yv = reinterpret_cast<const float4*>(y)[b * NN + i];
        float V = yv.x, m = yv.y, h = yv.z, n = yv.w;

        const float invC = invCs[i];
        const float acc  = V * rs[i] - wv[q * NN + i];    // sum_j w_ij (V_i - V_j)

        float gna = g_Na[i], gk = g_K[i], gl = g_L[i];
        float m2 = m * m, m3 = m2 * m;
        float n2 = n * n, n3 = n2 * n, n4 = n3 * n;
        float dVNa = V - E_Na[i];
        float dVK  = V - E_K[i];

        float Vdot = invC * (-gna * m3 * h * dVNa - gk * n4 * dVK - gl * (V - E_L[i]) + Ic[b]) + acc;
        float mdot = (m_inf[i] - m) / tau_m[i];
        float hdot = (h_inf[i] - h) / tau_h[i];
        float ndot = (n_inf[i] - n) / tau_n[i];

        reinterpret_cast<float4*>(ydot)[b * NN + i] = make_float4(Vdot, mdot, hdot, ndot);

        // J V-diagonal float4: {dvv + sumGC - w_ii, jm, jh, jn}
        float wii = gC[i * NN + i] * invC;
        float dvv = invC * (-gl - gna * h * m3 - gk * n4);
        float jm  = -invC * 3.f * gna * h * m2 * dVNa;
        float jh  = -invC * gna * m3 * dVNa;
        float jn  = -invC * 4.f * gk * n3 * dVK;

        // float4 index: b*(EE*NN) + (4i)*NN + i = b*65536 + 513*i
        reinterpret_cast<float4*>(J)[(unsigned)b * (EE * NN) + 513u * i] =
            make_float4(dvv + sumGC - wii, jm, jh, jn);
    }
}

// ---------------------------------------------------------------------
extern "C" void kernel_launch(void* const* d_in, const int* in_sizes, int n_in,
                              void* d_out, int out_size) {
    const float* y     = (const float*)d_in[0];
    const float* Ic    = (const float*)d_in[1];
    const float* C     = (const float*)d_in[2];
    const float* g_Na  = (const float*)d_in[3];
    const float* E_Na  = (const float*)d_in[4];
    const float* g_K   = (const float*)d_in[5];
    const float* E_K   = (const float*)d_in[6];
    const float* g_L   = (const float*)d_in[7];
    const float* E_L   = (const float*)d_in[8];
    const float* m_inf = (const float*)d_in[9];
    const float* tau_m = (const float*)d_in[10];
    const float* h_inf = (const float*)d_in[11];
    const float* tau_h = (const float*)d_in[12];
    const float* n_inf = (const float*)d_in[13];
    const float* tau_n = (const float*)d_in[14];
    const float* g_C   = (const float*)d_in[15];

    float* out  = (float*)d_out;
    float* ydot = out;                       // B*512 floats
    float* J    = out + (size_t)BB * EE;     // B*512*512 floats

    // ONE launch: y==0 plane carries the 64 point blocks (first waves),
    // y=1..128 planes carry the 268 MB fill.
    hh_fused_kernel<<<dim3(EE / 2, BB / 2 + 1), 256>>>(
        y, Ic, C, g_Na, E_Na, g_K, E_K, g_L, E_L,
        m_inf, tau_m, h_inf, tau_h, n_inf, tau_n, g_C, ydot, J);
}